// round 5
// baseline (speedup 1.0000x reference)
#include <cuda_runtime.h>
#include <math.h>

#define S_ 256
#define B_ 1024
#define D_ 64
#define Z_ 32
#define H_ 128
#define G_ 384
#define L_ 515
#define NSTEP 514

// ---------------- scratch (device globals; no allocation) ----------------
__device__ float g_hT[B_ * H_];
__device__ float g_zs[(size_t)L_ * B_ * Z_];
__device__ float g_kl[B_];
__device__ float g_part[2048];

// ============================ GRU scan =============================
// 128 CTAs x 384 threads. CTA owns 8 batches. thread = gate row g (0..383).
#define GRU_SMEM_FLOATS (384 * 128 + 512 + 1024 + 3072)

__global__ __launch_bounds__(384, 1) void gru_kernel(
    const float* __restrict__ xs, const float* __restrict__ Wih,
    const float* __restrict__ Whh, const float* __restrict__ bih,
    const float* __restrict__ bhh)
{
    extern __shared__ float sm[];
    float* sWhhT = sm;                   // [k*384 + g]
    float* sX    = sm + 384 * 128;       // [d*8 + j]
    float* sH    = sX + 512;             // [k*8 + j]
    float* sGate = sH + 1024;            // [g*8 + j]

    const int tid = threadIdx.x;
    const int g   = tid;
    const int b0  = blockIdx.x * 8;

    for (int idx = tid; idx < G_ * H_; idx += 384) {
        int gg = idx >> 7, k = idx & 127;
        sWhhT[k * 384 + gg] = Whh[idx];
    }
    for (int idx = tid; idx < 1024; idx += 384) sH[idx] = 0.0f;

    float wih[64];
#pragma unroll
    for (int k = 0; k < 64; ++k) wih[k] = Wih[g * 64 + k];
    const float bi = bih[g];
    const float bh = bhh[g];
    __syncthreads();

    for (int t = 0; t < S_; ++t) {
        const float* xsrc = xs + ((size_t)(S_ - 1 - t) * B_ + b0) * D_;
        for (int idx = tid; idx < 512; idx += 384) {
            int j = idx >> 6, d = idx & 63;
            sX[d * 8 + j] = xsrc[j * 64 + d];
        }
        __syncthreads();   // x ready; prev-step sH writes ordered

        float agi[8], ahh[8];
#pragma unroll
        for (int j = 0; j < 8; ++j) { agi[j] = 0.0f; ahh[j] = 0.0f; }

#pragma unroll
        for (int k = 0; k < 64; ++k) {
            float w = wih[k];
            float4 a  = *(const float4*)(sX + k * 8);
            float4 b4 = *(const float4*)(sX + k * 8 + 4);
            agi[0] += w * a.x;  agi[1] += w * a.y;  agi[2] += w * a.z;  agi[3] += w * a.w;
            agi[4] += w * b4.x; agi[5] += w * b4.y; agi[6] += w * b4.z; agi[7] += w * b4.w;
        }
#pragma unroll 8
        for (int k = 0; k < 128; ++k) {
            float w = sWhhT[k * 384 + g];
            float4 a  = *(const float4*)(sH + k * 8);
            float4 b4 = *(const float4*)(sH + k * 8 + 4);
            ahh[0] += w * a.x;  ahh[1] += w * a.y;  ahh[2] += w * a.z;  ahh[3] += w * a.w;
            ahh[4] += w * b4.x; ahh[5] += w * b4.y; ahh[6] += w * b4.z; ahh[7] += w * b4.w;
        }

        if (g < 256) {          // r, z gates
#pragma unroll
            for (int j = 0; j < 8; ++j) {
                float v = agi[j] + bi + ahh[j] + bh;
                sGate[g * 8 + j] = 1.0f / (1.0f + expf(-v));
            }
        } else {                // park h_n pre-activation
#pragma unroll
            for (int j = 0; j < 8; ++j) sGate[g * 8 + j] = ahh[j] + bh;
        }
        __syncthreads();        // r,z ready; all MAC reads done

        if (g >= 256) {         // n = tanh(i_n + r*h_n)
#pragma unroll
            for (int j = 0; j < 8; ++j) {
                float r = sGate[(g - 256) * 8 + j];
                sGate[g * 8 + j] = tanhf(agi[j] + bi + r * sGate[g * 8 + j]);
            }
        }
        __syncthreads();        // n ready

        if (g < 128) {          // h = (1-z)*n + z*h
#pragma unroll
            for (int j = 0; j < 8; ++j) {
                float zg = sGate[(g + 128) * 8 + j];
                float n  = sGate[(g + 256) * 8 + j];
                sH[g * 8 + j] = (1.0f - zg) * n + zg * sH[g * 8 + j];
            }
        }
        // next top-of-loop sync orders sH writes before MAC reads
    }
    if (g < 128) {
#pragma unroll
        for (int j = 0; j < 8; ++j)
            g_hT[(size_t)(b0 + j) * H_ + g] = sH[g * 8 + j];
    }
}

// ============================ encoder ==============================
// 16 CTAs x 64 threads; one batch per thread.
__global__ __launch_bounds__(64, 1) void enc_kernel(
    const float* __restrict__ encW, const float* __restrict__ encb,
    const float* __restrict__ qzW,  const float* __restrict__ qzb,
    const float* __restrict__ eps,  const float* __restrict__ pzm,
    const float* __restrict__ pzl)
{
    extern __shared__ float sm[];
    float* sHB  = sm;             // [k*64 + bl]
    float* sCtx = sm + 128 * 64;  // [c*64 + bl]
    const int tid = threadIdx.x;
    const int b0  = blockIdx.x * 64;
    const int b   = b0 + tid;

    for (int idx = tid; idx < 8192; idx += 64) {
        int bl = idx >> 7, k = idx & 127;
        sHB[k * 64 + bl] = g_hT[(size_t)(b0 + bl) * H_ + k];
    }
    __syncthreads();

    for (int c = 0; c < 64; ++c) {
        float acc = encb[c];
        const float* w = encW + c * 128;
#pragma unroll 8
        for (int k = 0; k < 128; ++k) acc += sHB[k * 64 + tid] * w[k];
        sCtx[c * 64 + tid] = acc;
    }

    float klb = 0.0f;
    for (int o = 0; o < 32; ++o) {
        float m  = qzb[o];
        float ls = qzb[o + 32];
        const float* wm = qzW + o * 64;
        const float* wl = qzW + (o + 32) * 64;
#pragma unroll 8
        for (int c = 0; c < 64; ++c) {
            float cv = sCtx[c * 64 + tid];
            m  += cv * wm[c];
            ls += cv * wl[c];
        }
        float z0 = m + expf(ls) * eps[(size_t)b * Z_ + o];
        g_zs[(size_t)b * Z_ + o] = z0;
        float dm = m - pzm[o];
        float pl = pzl[o];
        klb += pl - ls + (expf(2.0f * ls) + dm * dm) / (2.0f * expf(2.0f * pl)) - 0.5f;
    }
    g_kl[b] = klb;
}

// ============================ SDE scan =============================
// 128 CTAs x 256 threads, 8 batches/CTA, all weights in SMEM.
#define SDE_SMEM_FLOATS 41412

__global__ __launch_bounds__(256, 1) void sde_kernel(
    const float* __restrict__ ts,  const float* __restrict__ dWg,
    const float* __restrict__ fW1, const float* __restrict__ fb1,
    const float* __restrict__ fW2, const float* __restrict__ fb2,
    const float* __restrict__ fW3, const float* __restrict__ fb3,
    const float* __restrict__ gW1, const float* __restrict__ gb1,
    const float* __restrict__ gW2, const float* __restrict__ gb2)
{
    extern __shared__ float sm[];
    float* sFW1T = sm;              // 33x128 [k*128+i]
    float* sGW1T = sm + 4224;
    float* sFW2T = sm + 8448;       // [k*128+i]
    float* sFW3T = sm + 24832;      // [k*32+o]
    float* sGW2T = sm + 28928;      // [k*32+o]
    float* sFB1  = sm + 33024;
    float* sFB2  = sm + 33152;
    float* sGB1  = sm + 33280;
    float* sFB3  = sm + 33408;
    float* sGB2  = sm + 33440;
    float* sTS   = sm + 33472;      // 516
    float* sZ    = sm + 33988;      // [o*8+j]
    float* sH1   = sm + 34244;      // [i*8+j]
    float* sGH   = sm + 35268;
    float* sH2   = sm + 36292;
    float* sP2   = sm + 37316;      // [half*1024 + i*8+j]
    float* sPF   = sm + 39364;      // [i*8+j], i = q*32+o
    float* sPG   = sm + 40388;

    const int tid = threadIdx.x;
    const int b0  = blockIdx.x * 8;
    const int hv  = tid >> 7;       // 0: f branch, 1: g branch
    const int i   = tid & 127;
    const int oo  = tid & 31;       // for S5 / dW prefetch
    const int jj  = tid >> 5;       // 0..7

    for (int idx = tid; idx < 128 * 33; idx += 256) {
        int ii = idx / 33, k = idx % 33;
        sFW1T[k * 128 + ii] = fW1[idx];
        sGW1T[k * 128 + ii] = gW1[idx];
    }
    for (int idx = tid; idx < 16384; idx += 256) {
        int ii = idx >> 7, k = idx & 127;
        sFW2T[k * 128 + ii] = fW2[idx];
    }
    for (int idx = tid; idx < 4096; idx += 256) {
        int o = idx >> 7, k = idx & 127;
        sFW3T[k * 32 + o] = fW3[idx];
        sGW2T[k * 32 + o] = gW2[idx];
    }
    if (tid < 128) { sFB1[tid] = fb1[tid]; sFB2[tid] = fb2[tid]; sGB1[tid] = gb1[tid]; }
    else if (tid < 160) { int o = tid - 128; sFB3[o] = fb3[o]; sGB2[o] = gb2[o]; }
    for (int idx = tid; idx < L_; idx += 256) sTS[idx] = ts[idx];
    for (int idx = tid; idx < 256; idx += 256) {
        int j = idx >> 5, o = idx & 31;
        sZ[o * 8 + j] = g_zs[(size_t)(b0 + j) * Z_ + o];
    }
    __syncthreads();

    const float* W1T = hv ? sGW1T : sFW1T;
    const float* B1  = hv ? sGB1  : sFB1;
    float* dst1      = hv ? sGH   : sH1;

    for (int t = 0; t < NSTEP; ++t) {
        // prefetch this thread's dW element (used in S5; ~4.5K cyc of cover)
        float dwv = dWg[((size_t)t * B_ + b0 + jj) * Z_ + oo];
        const float tval = sTS[t];
        const float dt   = sTS[t + 1] - tval;
        const float sdt  = sqrtf(dt);

        // ---- S1: layer-1 of f (half0) / g (half1): relu(W1 @ [t;z] + b)
        {
            float bb = B1[i];
            float w0 = W1T[i];
            float acc[8];
#pragma unroll
            for (int j = 0; j < 8; ++j) acc[j] = bb + w0 * tval;
#pragma unroll 8
            for (int k = 0; k < 32; ++k) {
                float w = W1T[(k + 1) * 128 + i];
                float4 a  = *(const float4*)(sZ + k * 8);
                float4 b4 = *(const float4*)(sZ + k * 8 + 4);
                acc[0] += w * a.x;  acc[1] += w * a.y;  acc[2] += w * a.z;  acc[3] += w * a.w;
                acc[4] += w * b4.x; acc[5] += w * b4.y; acc[6] += w * b4.z; acc[7] += w * b4.w;
            }
#pragma unroll
            for (int j = 0; j < 8; ++j) dst1[i * 8 + j] = fmaxf(acc[j], 0.0f);
        }
        __syncthreads();

        // ---- S2: f_W2 k-split partials (both halves) + diff partials (half1)
        {
            const int kb = hv * 64;
            float acc[8];
#pragma unroll
            for (int j = 0; j < 8; ++j) acc[j] = 0.0f;
#pragma unroll 8
            for (int k = 0; k < 64; ++k) {
                float w = sFW2T[(kb + k) * 128 + i];
                float4 a  = *(const float4*)(sH1 + (kb + k) * 8);
                float4 b4 = *(const float4*)(sH1 + (kb + k) * 8 + 4);
                acc[0] += w * a.x;  acc[1] += w * a.y;  acc[2] += w * a.z;  acc[3] += w * a.w;
                acc[4] += w * b4.x; acc[5] += w * b4.y; acc[6] += w * b4.z; acc[7] += w * b4.w;
            }
#pragma unroll
            for (int j = 0; j < 8; ++j) sP2[hv * 1024 + i * 8 + j] = acc[j];

            if (hv) {   // diff partial: o = i&31, k in [(i>>5)*32, +32)
                const int o  = i & 31;
                const int kq = (i >> 5) * 32;
                float pg[8];
#pragma unroll
                for (int j = 0; j < 8; ++j) pg[j] = 0.0f;
#pragma unroll 8
                for (int k = 0; k < 32; ++k) {
                    float w = sGW2T[(kq + k) * 32 + o];
                    float4 a  = *(const float4*)(sGH + (kq + k) * 8);
                    float4 b4 = *(const float4*)(sGH + (kq + k) * 8 + 4);
                    pg[0] += w * a.x;  pg[1] += w * a.y;  pg[2] += w * a.z;  pg[3] += w * a.w;
                    pg[4] += w * b4.x; pg[5] += w * b4.y; pg[6] += w * b4.z; pg[7] += w * b4.w;
                }
#pragma unroll
                for (int j = 0; j < 8; ++j) sPG[i * 8 + j] = pg[j];
            }
        }
        __syncthreads();

        // ---- S3: h2 = relu(fb2 + p0 + p1)  (half0)
        if (hv == 0) {
            float bb = sFB2[i];
#pragma unroll
            for (int j = 0; j < 8; ++j)
                sH2[i * 8 + j] = fmaxf(bb + sP2[i * 8 + j] + sP2[1024 + i * 8 + j], 0.0f);
        }
        __syncthreads();

        // ---- S4: drift partials (half0)
        if (hv == 0) {
            const int o  = i & 31;
            const int kq = (i >> 5) * 32;
            float pf[8];
#pragma unroll
            for (int j = 0; j < 8; ++j) pf[j] = 0.0f;
#pragma unroll 8
            for (int k = 0; k < 32; ++k) {
                float w = sFW3T[(kq + k) * 32 + o];
                float4 a  = *(const float4*)(sH2 + (kq + k) * 8);
                float4 b4 = *(const float4*)(sH2 + (kq + k) * 8 + 4);
                pf[0] += w * a.x;  pf[1] += w * a.y;  pf[2] += w * a.z;  pf[3] += w * a.w;
                pf[4] += w * b4.x; pf[5] += w * b4.y; pf[6] += w * b4.z; pf[7] += w * b4.w;
            }
#pragma unroll
            for (int j = 0; j < 8; ++j) sPF[i * 8 + j] = pf[j];
        }
        __syncthreads();

        // ---- S5: reduce + z update (all 256 threads: one (o,j) each)
        {
            float drift = sFB3[oo] + sPF[oo * 8 + jj] + sPF[(32 + oo) * 8 + jj]
                        + sPF[(64 + oo) * 8 + jj] + sPF[(96 + oo) * 8 + jj];
            float diff  = sGB2[oo] + sPG[oo * 8 + jj] + sPG[(32 + oo) * 8 + jj]
                        + sPG[(64 + oo) * 8 + jj] + sPG[(96 + oo) * 8 + jj];
            float zn = sZ[oo * 8 + jj] + drift * dt + diff * (sdt * dwv);
            sZ[oo * 8 + jj] = zn;
            g_zs[((size_t)(t + 1) * B_ + b0 + jj) * Z_ + oo] = zn;
        }
        __syncthreads();
    }
}

// ============================ projection ===========================
// grid (511, 8): row l = bx+2, 128 batches per CTA.
__global__ __launch_bounds__(256, 1) void proj_kernel(
    const float* __restrict__ projW, const float* __restrict__ projb,
    const float* __restrict__ xs, float* __restrict__ out)
{
    __shared__ float sZt[128 * 33];
    __shared__ float sW[64 * 32];
    __shared__ float sB[64];
    __shared__ float sRed[256];
    const int l   = blockIdx.x + 2;
    const int b0  = blockIdx.y * 128;
    const int tid = threadIdx.x;

    for (int idx = tid; idx < 4096; idx += 256) {
        int bl = idx >> 5, o = idx & 31;
        sZt[bl * 33 + o] = g_zs[((size_t)l * B_ + b0 + bl) * Z_ + o];
    }
    for (int idx = tid; idx < 2048; idx += 256) sW[idx] = projW[idx];
    if (tid < 64) sB[tid] = projb[tid];
    __syncthreads();

    const int bl = tid >> 1, dh = tid & 1;
    const float* zrow = sZt + bl * 33;
    const bool odd = (l & 1);
    float lsum = 0.0f;

    for (int dd = 0; dd < 32; ++dd) {
        int d = dh * 32 + dd;
        const float* wrow = sW + d * 32;
        float acc = sB[d];
#pragma unroll 8
        for (int o = 0; o < 32; ++o) acc += zrow[o] * wrow[o];
        if (odd) {
            size_t oi = 2 + (((size_t)((l - 3) >> 1) * B_ + b0 + bl) * D_ + d);
            out[oi] = acc;
        } else {
            float dv = acc - xs[((size_t)((l - 2) >> 1) * B_ + b0 + bl) * D_ + d];
            lsum += dv * dv;
        }
    }
    if (!odd) {
        sRed[tid] = lsum; __syncthreads();
        for (int s = 128; s > 0; s >>= 1) {
            if (tid < s) sRed[tid] += sRed[tid + s];
            __syncthreads();
        }
        if (tid == 0) g_part[((l - 2) >> 1) * 8 + blockIdx.y] = sRed[0];
    }
}

// ============================ final scalars ========================
__global__ __launch_bounds__(256, 1) void final_kernel(float* __restrict__ out)
{
    __shared__ float sRed[256];
    const int tid = threadIdx.x;
    float s = 0.0f;
    for (int idx = tid; idx < 2048; idx += 256) s += g_part[idx];
    sRed[tid] = s; __syncthreads();
    for (int st = 128; st > 0; st >>= 1) {
        if (tid < st) sRed[tid] += sRed[tid + st];
        __syncthreads();
    }
    if (tid == 0) out[0] = sRed[0] / 16777216.0f;  // 256*1024*64
    __syncthreads();

    s = 0.0f;
    for (int idx = tid; idx < 1024; idx += 256) s += g_kl[idx];
    sRed[tid] = s; __syncthreads();
    for (int st = 128; st > 0; st >>= 1) {
        if (tid < st) sRed[tid] += sRed[tid + st];
        __syncthreads();
    }
    if (tid == 0) out[1] = sRed[0] / 1024.0f;
}

// ============================ launch ===============================
extern "C" void kernel_launch(void* const* d_in, const int* in_sizes, int n_in,
                              void* d_out, int out_size)
{
    const float* xs    = (const float*)d_in[0];
    const float* extts = (const float*)d_in[1];
    const float* eps   = (const float*)d_in[2];
    const float* dWg   = (const float*)d_in[3];
    const float* Wih   = (const float*)d_in[4];
    const float* Whh   = (const float*)d_in[5];
    const float* bih   = (const float*)d_in[6];
    const float* bhh   = (const float*)d_in[7];
    const float* encW  = (const float*)d_in[8];
    const float* encb  = (const float*)d_in[9];
    const float* qzW   = (const float*)d_in[10];
    const float* qzb   = (const float*)d_in[11];
    const float* fW1   = (const float*)d_in[12];
    const float* fb1   = (const float*)d_in[13];
    const float* fW2   = (const float*)d_in[14];
    const float* fb2   = (const float*)d_in[15];
    const float* fW3   = (const float*)d_in[16];
    const float* fb3   = (const float*)d_in[17];
    const float* gW1   = (const float*)d_in[18];
    const float* gb1   = (const float*)d_in[19];
    const float* gW2   = (const float*)d_in[20];
    const float* gb2   = (const float*)d_in[21];
    const float* projW = (const float*)d_in[22];
    const float* projb = (const float*)d_in[23];
    const float* pzm   = (const float*)d_in[24];
    const float* pzl   = (const float*)d_in[25];
    float* out = (float*)d_out;

    cudaFuncSetAttribute(gru_kernel, cudaFuncAttributeMaxDynamicSharedMemorySize,
                         GRU_SMEM_FLOATS * 4);
    cudaFuncSetAttribute(enc_kernel, cudaFuncAttributeMaxDynamicSharedMemorySize,
                         (128 * 64 + 64 * 64) * 4);
    cudaFuncSetAttribute(sde_kernel, cudaFuncAttributeMaxDynamicSharedMemorySize,
                         SDE_SMEM_FLOATS * 4);

    gru_kernel<<<128, 384, GRU_SMEM_FLOATS * 4>>>(xs, Wih, Whh, bih, bhh);
    enc_kernel<<<16, 64, (128 * 64 + 64 * 64) * 4>>>(encW, encb, qzW, qzb, eps, pzm, pzl);
    sde_kernel<<<128, 256, SDE_SMEM_FLOATS * 4>>>(extts, dWg, fW1, fb1, fW2, fb2,
                                                  fW3, fb3, gW1, gb1, gW2, gb2);
    dim3 pg(511, 8);
    proj_kernel<<<pg, 256>>>(projW, projb, xs, out);
    final_kernel<<<1, 256>>>(out);
}

// round 8
// speedup vs baseline: 1.0812x; 1.0812x over previous
#include <cuda_runtime.h>
#include <math.h>

#define S_ 256
#define B_ 1024
#define D_ 64
#define Z_ 32
#define H_ 128
#define G_ 384
#define L_ 515
#define NSTEP 514

// ---------------- scratch (device globals; no allocation) ----------------
__device__ float g_hT[B_ * H_];
__device__ float g_zs[(size_t)L_ * B_ * Z_];
__device__ float g_kl[B_];
__device__ float g_part[1024];

// ---------------- packed f32x2 helpers (sm_103a) ----------------
__device__ __forceinline__ void ffma2(unsigned long long& d,
                                      unsigned long long a,
                                      unsigned long long b) {
    asm("fma.rn.f32x2 %0, %1, %2, %0;" : "+l"(d) : "l"(a), "l"(b));
}
__device__ __forceinline__ unsigned long long pack2(float v) {
    unsigned long long r;
    asm("mov.b64 %0, {%1, %1};" : "=l"(r) : "f"(v));
    return r;
}
__device__ __forceinline__ unsigned long long pack2(float a, float b) {
    unsigned long long r;
    asm("mov.b64 %0, {%1, %2};" : "=l"(r) : "f"(a), "f"(b));
    return r;
}
__device__ __forceinline__ float2 unpack2(unsigned long long v) {
    float2 r;
    asm("mov.b64 {%0, %1}, %2;" : "=f"(r.x), "=f"(r.y) : "l"(v));
    return r;
}

// ============================ GRU scan =============================
// 128 CTAs x 384 threads. CTA owns 8 batches. thread = gate row g (0..383).
#define GRU_SMEM_FLOATS (384 * 128 + 512 + 1024 + 3072)

__global__ __launch_bounds__(384, 1) void gru_kernel(
    const float* __restrict__ xs, const float* __restrict__ Wih,
    const float* __restrict__ Whh, const float* __restrict__ bih,
    const float* __restrict__ bhh)
{
    extern __shared__ float sm[];
    float* sWhhT = sm;                   // [k*384 + g]
    float* sX    = sm + 384 * 128;       // [d*8 + j]
    float* sH    = sX + 512;             // [k*8 + j]
    float* sGate = sH + 1024;            // [g*8 + j]

    const int tid = threadIdx.x;
    const int g   = tid;
    const int b0  = blockIdx.x * 8;

    for (int idx = tid; idx < G_ * H_; idx += 384) {
        int gg = idx >> 7, k = idx & 127;
        sWhhT[k * 384 + gg] = Whh[idx];
    }
    for (int idx = tid; idx < 1024; idx += 384) sH[idx] = 0.0f;

    float wih[64];
#pragma unroll
    for (int k = 0; k < 64; ++k) wih[k] = Wih[g * 64 + k];
    const float bi = bih[g];
    const float bh = bhh[g];
    __syncthreads();

    for (int t = 0; t < S_; ++t) {
        const float* xsrc = xs + ((size_t)(S_ - 1 - t) * B_ + b0) * D_;
        for (int idx = tid; idx < 512; idx += 384) {
            int j = idx >> 6, d = idx & 63;
            sX[d * 8 + j] = xsrc[j * 64 + d];
        }
        __syncthreads();   // x ready; prev-step sH writes ordered

        unsigned long long agi2[4] = {0ull, 0ull, 0ull, 0ull};
        unsigned long long ahh2[4] = {0ull, 0ull, 0ull, 0ull};

#pragma unroll
        for (int k = 0; k < 64; ++k) {
            unsigned long long wp = pack2(wih[k]);
            const ulonglong2* xp = (const ulonglong2*)(sX + k * 8);
            ulonglong2 u0 = xp[0], u1 = xp[1];
            ffma2(agi2[0], wp, u0.x); ffma2(agi2[1], wp, u0.y);
            ffma2(agi2[2], wp, u1.x); ffma2(agi2[3], wp, u1.y);
        }
#pragma unroll 8
        for (int k = 0; k < 128; ++k) {
            unsigned long long wp = pack2(sWhhT[k * 384 + g]);
            const ulonglong2* hp = (const ulonglong2*)(sH + k * 8);
            ulonglong2 u0 = hp[0], u1 = hp[1];
            ffma2(ahh2[0], wp, u0.x); ffma2(ahh2[1], wp, u0.y);
            ffma2(ahh2[2], wp, u1.x); ffma2(ahh2[3], wp, u1.y);
        }

        float agi[8], ahh[8];
#pragma unroll
        for (int j = 0; j < 4; ++j) {
            float2 a = unpack2(agi2[j]); agi[2 * j] = a.x; agi[2 * j + 1] = a.y;
            float2 b = unpack2(ahh2[j]); ahh[2 * j] = b.x; ahh[2 * j + 1] = b.y;
        }

        if (g < 256) {          // r, z gates
#pragma unroll
            for (int j = 0; j < 8; ++j) {
                float v = agi[j] + bi + ahh[j] + bh;
                sGate[g * 8 + j] = 1.0f / (1.0f + expf(-v));
            }
        } else {                // park h_n pre-activation
#pragma unroll
            for (int j = 0; j < 8; ++j) sGate[g * 8 + j] = ahh[j] + bh;
        }
        __syncthreads();        // r,z ready; all MAC reads done

        if (g >= 256) {         // n = tanh(i_n + r*h_n)
#pragma unroll
            for (int j = 0; j < 8; ++j) {
                float r = sGate[(g - 256) * 8 + j];
                sGate[g * 8 + j] = tanhf(agi[j] + bi + r * sGate[g * 8 + j]);
            }
        }
        __syncthreads();        // n ready

        if (g < 128) {          // h = (1-z)*n + z*h
#pragma unroll
            for (int j = 0; j < 8; ++j) {
                float zg = sGate[(g + 128) * 8 + j];
                float n  = sGate[(g + 256) * 8 + j];
                sH[g * 8 + j] = (1.0f - zg) * n + zg * sH[g * 8 + j];
            }
        }
    }
    if (g < 128) {
#pragma unroll
        for (int j = 0; j < 8; ++j)
            g_hT[(size_t)(b0 + j) * H_ + g] = sH[g * 8 + j];
    }
}

// ============================ encoder ==============================
__global__ __launch_bounds__(64, 1) void enc_kernel(
    const float* __restrict__ encW, const float* __restrict__ encb,
    const float* __restrict__ qzW,  const float* __restrict__ qzb,
    const float* __restrict__ eps,  const float* __restrict__ pzm,
    const float* __restrict__ pzl)
{
    extern __shared__ float sm[];
    float* sHB  = sm;             // [k*64 + bl]
    float* sCtx = sm + 128 * 64;  // [c*64 + bl]
    const int tid = threadIdx.x;
    const int b0  = blockIdx.x * 64;
    const int b   = b0 + tid;

    for (int idx = tid; idx < 8192; idx += 64) {
        int bl = idx >> 7, k = idx & 127;
        sHB[k * 64 + bl] = g_hT[(size_t)(b0 + bl) * H_ + k];
    }
    __syncthreads();

    for (int c = 0; c < 64; ++c) {
        float acc = encb[c];
        const float* w = encW + c * 128;
#pragma unroll 8
        for (int k = 0; k < 128; ++k) acc += sHB[k * 64 + tid] * w[k];
        sCtx[c * 64 + tid] = acc;
    }

    float klb = 0.0f;
    for (int o = 0; o < 32; ++o) {
        float m  = qzb[o];
        float ls = qzb[o + 32];
        const float* wm = qzW + o * 64;
        const float* wl = qzW + (o + 32) * 64;
#pragma unroll 8
        for (int c = 0; c < 64; ++c) {
            float cv = sCtx[c * 64 + tid];
            m  += cv * wm[c];
            ls += cv * wl[c];
        }
        float z0 = m + expf(ls) * eps[(size_t)b * Z_ + o];
        g_zs[(size_t)b * Z_ + o] = z0;
        float dm = m - pzm[o];
        float pl = pzl[o];
        klb += pl - ls + (expf(2.0f * ls) + dm * dm) / (2.0f * expf(2.0f * pl)) - 0.5f;
    }
    g_kl[b] = klb;
}

// ============================ SDE scan =============================
#define SDE_SMEM_FLOATS 41412

__global__ __launch_bounds__(256, 1) void sde_kernel(
    const float* __restrict__ ts,  const float* __restrict__ dWg,
    const float* __restrict__ fW1, const float* __restrict__ fb1,
    const float* __restrict__ fW2, const float* __restrict__ fb2,
    const float* __restrict__ fW3, const float* __restrict__ fb3,
    const float* __restrict__ gW1, const float* __restrict__ gb1,
    const float* __restrict__ gW2, const float* __restrict__ gb2)
{
    extern __shared__ float sm[];
    float* sFW1T = sm;              // 33x128 [k*128+i]
    float* sGW1T = sm + 4224;
    float* sFW2T = sm + 8448;       // [k*128+i]
    float* sFW3T = sm + 24832;      // [k*32+o]
    float* sGW2T = sm + 28928;      // [k*32+o]
    float* sFB1  = sm + 33024;
    float* sFB2  = sm + 33152;
    float* sGB1  = sm + 33280;
    float* sFB3  = sm + 33408;
    float* sGB2  = sm + 33440;
    float* sTS   = sm + 33472;      // 516
    float* sZ    = sm + 33988;      // [o*8+j]
    float* sH1   = sm + 34244;      // [i*8+j]
    float* sGH   = sm + 35268;
    float* sH2   = sm + 36292;
    float* sP2   = sm + 37316;      // [half*1024 + i*8+j]
    float* sPF   = sm + 39364;      // [i*8+j], i = q*32+o
    float* sPG   = sm + 40388;

    const int tid = threadIdx.x;
    const int b0  = blockIdx.x * 8;
    const int hv  = tid >> 7;       // 0: f branch, 1: g branch
    const int i   = tid & 127;
    const int oo  = tid & 31;
    const int jj  = tid >> 5;

    for (int idx = tid; idx < 128 * 33; idx += 256) {
        int ii = idx / 33, k = idx % 33;
        sFW1T[k * 128 + ii] = fW1[idx];
        sGW1T[k * 128 + ii] = gW1[idx];
    }
    for (int idx = tid; idx < 16384; idx += 256) {
        int ii = idx >> 7, k = idx & 127;
        sFW2T[k * 128 + ii] = fW2[idx];
    }
    for (int idx = tid; idx < 4096; idx += 256) {
        int o = idx >> 7, k = idx & 127;
        sFW3T[k * 32 + o] = fW3[idx];
        sGW2T[k * 32 + o] = gW2[idx];
    }
    if (tid < 128) { sFB1[tid] = fb1[tid]; sFB2[tid] = fb2[tid]; sGB1[tid] = gb1[tid]; }
    else if (tid < 160) { int o = tid - 128; sFB3[o] = fb3[o]; sGB2[o] = gb2[o]; }
    for (int idx = tid; idx < L_; idx += 256) sTS[idx] = ts[idx];
    for (int idx = tid; idx < 256; idx += 256) {
        int j = idx >> 5, o = idx & 31;
        sZ[o * 8 + j] = g_zs[(size_t)(b0 + j) * Z_ + o];
    }
    __syncthreads();

    const float* W1T = hv ? sGW1T : sFW1T;
    const float* B1  = hv ? sGB1  : sFB1;
    float* dst1      = hv ? sGH   : sH1;

    for (int t = 0; t < NSTEP; ++t) {
        float dwv = dWg[((size_t)t * B_ + b0 + jj) * Z_ + oo];
        const float tval = sTS[t];
        const float dt   = sTS[t + 1] - tval;
        const float sdt  = sqrtf(dt);

        // ---- S1: layer-1 of f (half0) / g (half1): relu(W1 @ [t;z] + b)
        {
            float iv = fmaf(W1T[i], tval, B1[i]);
            unsigned long long acc2[4];
            unsigned long long ivp = pack2(iv);
#pragma unroll
            for (int j = 0; j < 4; ++j) acc2[j] = ivp;
#pragma unroll 8
            for (int k = 0; k < 32; ++k) {
                unsigned long long wp = pack2(W1T[(k + 1) * 128 + i]);
                const ulonglong2* zp = (const ulonglong2*)(sZ + k * 8);
                ulonglong2 u0 = zp[0], u1 = zp[1];
                ffma2(acc2[0], wp, u0.x); ffma2(acc2[1], wp, u0.y);
                ffma2(acc2[2], wp, u1.x); ffma2(acc2[3], wp, u1.y);
            }
            float2 r0 = unpack2(acc2[0]), r1 = unpack2(acc2[1]);
            float2 r2 = unpack2(acc2[2]), r3 = unpack2(acc2[3]);
            float4 v0 = make_float4(fmaxf(r0.x, 0.f), fmaxf(r0.y, 0.f),
                                    fmaxf(r1.x, 0.f), fmaxf(r1.y, 0.f));
            float4 v1 = make_float4(fmaxf(r2.x, 0.f), fmaxf(r2.y, 0.f),
                                    fmaxf(r3.x, 0.f), fmaxf(r3.y, 0.f));
            *(float4*)(dst1 + i * 8)     = v0;
            *(float4*)(dst1 + i * 8 + 4) = v1;
        }
        __syncthreads();

        // ---- S2: f_W2 k-split partials (both halves) + diff partials (half1)
        {
            const int kb = hv * 64;
            unsigned long long acc2[4] = {0ull, 0ull, 0ull, 0ull};
#pragma unroll 8
            for (int k = 0; k < 64; ++k) {
                unsigned long long wp = pack2(sFW2T[(kb + k) * 128 + i]);
                const ulonglong2* hp = (const ulonglong2*)(sH1 + (kb + k) * 8);
                ulonglong2 u0 = hp[0], u1 = hp[1];
                ffma2(acc2[0], wp, u0.x); ffma2(acc2[1], wp, u0.y);
                ffma2(acc2[2], wp, u1.x); ffma2(acc2[3], wp, u1.y);
            }
            ulonglong2 s0; s0.x = acc2[0]; s0.y = acc2[1];
            ulonglong2 s1; s1.x = acc2[2]; s1.y = acc2[3];
            *(ulonglong2*)(sP2 + hv * 1024 + i * 8)     = s0;
            *(ulonglong2*)(sP2 + hv * 1024 + i * 8 + 4) = s1;

            if (hv) {   // diff partial: o = i&31, k in [(i>>5)*32, +32)
                const int kq = (i >> 5) * 32;
                const int o  = i & 31;
                unsigned long long pg2[4] = {0ull, 0ull, 0ull, 0ull};
#pragma unroll 8
                for (int k = 0; k < 32; ++k) {
                    unsigned long long wp = pack2(sGW2T[(kq + k) * 32 + o]);
                    const ulonglong2* gp = (const ulonglong2*)(sGH + (kq + k) * 8);
                    ulonglong2 u0 = gp[0], u1 = gp[1];
                    ffma2(pg2[0], wp, u0.x); ffma2(pg2[1], wp, u0.y);
                    ffma2(pg2[2], wp, u1.x); ffma2(pg2[3], wp, u1.y);
                }
                ulonglong2 g0; g0.x = pg2[0]; g0.y = pg2[1];
                ulonglong2 g1; g1.x = pg2[2]; g1.y = pg2[3];
                *(ulonglong2*)(sPG + i * 8)     = g0;
                *(ulonglong2*)(sPG + i * 8 + 4) = g1;
            }
        }
        __syncthreads();

        // ---- S3: h2 = relu(fb2 + p0 + p1)  (half0)
        if (hv == 0) {
            float bb = sFB2[i];
#pragma unroll
            for (int j = 0; j < 8; ++j)
                sH2[i * 8 + j] = fmaxf(bb + sP2[i * 8 + j] + sP2[1024 + i * 8 + j], 0.0f);
        }
        __syncthreads();

        // ---- S4: drift partials (half0)
        if (hv == 0) {
            const int kq = (i >> 5) * 32;
            const int o  = i & 31;
            unsigned long long pf2[4] = {0ull, 0ull, 0ull, 0ull};
#pragma unroll 8
            for (int k = 0; k < 32; ++k) {
                unsigned long long wp = pack2(sFW3T[(kq + k) * 32 + o]);
                const ulonglong2* hp = (const ulonglong2*)(sH2 + (kq + k) * 8);
                ulonglong2 u0 = hp[0], u1 = hp[1];
                ffma2(pf2[0], wp, u0.x); ffma2(pf2[1], wp, u0.y);
                ffma2(pf2[2], wp, u1.x); ffma2(pf2[3], wp, u1.y);
            }
            ulonglong2 f0; f0.x = pf2[0]; f0.y = pf2[1];
            ulonglong2 f1; f1.x = pf2[2]; f1.y = pf2[3];
            *(ulonglong2*)(sPF + i * 8)     = f0;
            *(ulonglong2*)(sPF + i * 8 + 4) = f1;
        }
        __syncthreads();

        // ---- S5: reduce + z update (all 256 threads: one (o,j) each)
        {
            float drift = sFB3[oo] + sPF[oo * 8 + jj] + sPF[(32 + oo) * 8 + jj]
                        + sPF[(64 + oo) * 8 + jj] + sPF[(96 + oo) * 8 + jj];
            float diff  = sGB2[oo] + sPG[oo * 8 + jj] + sPG[(32 + oo) * 8 + jj]
                        + sPG[(64 + oo) * 8 + jj] + sPG[(96 + oo) * 8 + jj];
            float zn = sZ[oo * 8 + jj] + drift * dt + diff * (sdt * dwv);
            sZ[oo * 8 + jj] = zn;
            g_zs[((size_t)(t + 1) * B_ + b0 + jj) * Z_ + oo] = zn;
        }
        __syncthreads();
    }
}

// ============================ projection ===========================
// grid (511, 4): row l = bx+2, 256 batches per CTA, one thread per batch.
__global__ __launch_bounds__(256, 1) void proj_kernel(
    const float* __restrict__ projW, const float* __restrict__ projb,
    const float* __restrict__ xs, float* __restrict__ out)
{
    __shared__ float sBuf[256 * 33];   // z staging, then out/xs chunk staging
    __shared__ float sW[64 * 32];
    __shared__ float sB[64];
    __shared__ float sRed[256];
    const int l   = blockIdx.x + 2;
    const int b0  = blockIdx.y * 256;
    const int tid = threadIdx.x;

    // stage z coalesced, padded stride 33
    for (int idx = tid; idx < 8192; idx += 256) {
        int bl = idx >> 5, o = idx & 31;
        sBuf[bl * 33 + o] = g_zs[((size_t)l * B_ + b0 + bl) * Z_ + o];
    }
    for (int idx = tid; idx < 2048; idx += 256) sW[idx] = projW[idx];
    if (tid < 64) sB[tid] = projb[tid];
    __syncthreads();

    // z into registers (own row, conflict-free via pad)
    unsigned long long z2[16];
    {
        const float* zr = sBuf + tid * 33;
#pragma unroll
        for (int p = 0; p < 16; ++p) z2[p] = pack2(zr[2 * p], zr[2 * p + 1]);
    }
    __syncthreads();   // everyone has z in regs; sBuf reusable

    const bool odd = (l & 1);
    float lsum = 0.0f;

    for (int half = 0; half < 2; ++half) {
        if (!odd) {
            // stage xs chunk coalesced
            const size_t xbase = ((size_t)((l - 2) >> 1) * B_ + b0) * D_ + half * 32;
            for (int idx = tid; idx < 8192; idx += 256) {
                int bl = idx >> 5, dc = idx & 31;
                sBuf[bl * 33 + dc] = xs[xbase + (size_t)bl * D_ + dc];
            }
            __syncthreads();
        }
#pragma unroll 4
        for (int dc = 0; dc < 32; ++dc) {
            const int d = half * 32 + dc;
            unsigned long long a2 = 0ull, b2 = 0ull;
            const ulonglong2* wp = (const ulonglong2*)(sW + d * 32);
#pragma unroll
            for (int q = 0; q < 8; ++q) {
                ulonglong2 w = wp[q];          // broadcast
                ffma2(a2, z2[2 * q],     w.x);
                ffma2(b2, z2[2 * q + 1], w.y);
            }
            float2 pa = unpack2(a2), pb = unpack2(b2);
            float acc = sB[d] + pa.x + pa.y + pb.x + pb.y;
            if (odd) {
                sBuf[tid * 33 + dc] = acc;     // own row
            } else {
                float dv = acc - sBuf[tid * 33 + dc];
                lsum = fmaf(dv, dv, lsum);
            }
        }
        __syncthreads();
        if (odd) {
            // cooperative coalesced store of this 32-col chunk
            const size_t obase = 2 + (((size_t)((l - 3) >> 1) * B_ + b0) * D_ + half * 32);
            for (int idx = tid; idx < 8192; idx += 256) {
                int bl = idx >> 5, dc = idx & 31;
                out[obase + (size_t)bl * D_ + dc] = sBuf[bl * 33 + dc];
            }
            __syncthreads();
        }
    }

    if (!odd) {
        sRed[tid] = lsum; __syncthreads();
        for (int s = 128; s > 0; s >>= 1) {
            if (tid < s) sRed[tid] += sRed[tid + s];
            __syncthreads();
        }
        if (tid == 0) g_part[((l - 2) >> 1) * 4 + blockIdx.y] = sRed[0];
    }
}

// ============================ final scalars ========================
__global__ __launch_bounds__(256, 1) void final_kernel(float* __restrict__ out)
{
    __shared__ float sRed[256];
    const int tid = threadIdx.x;
    float s = 0.0f;
    for (int idx = tid; idx < 1024; idx += 256) s += g_part[idx];
    sRed[tid] = s; __syncthreads();
    for (int st = 128; st > 0; st >>= 1) {
        if (tid < st) sRed[tid] += sRed[tid + st];
        __syncthreads();
    }
    if (tid == 0) out[0] = sRed[0] / 16777216.0f;  // 256*1024*64
    __syncthreads();

    s = 0.0f;
    for (int idx = tid; idx < 1024; idx += 256) s += g_kl[idx];
    sRed[tid] = s; __syncthreads();
    for (int st = 128; st > 0; st >>= 1) {
        if (tid < st) sRed[tid] += sRed[tid + st];
        __syncthreads();
    }
    if (tid == 0) out[1] = sRed[0] / 1024.0f;
}

// ============================ launch ===============================
extern "C" void kernel_launch(void* const* d_in, const int* in_sizes, int n_in,
                              void* d_out, int out_size)
{
    const float* xs    = (const float*)d_in[0];
    const float* extts = (const float*)d_in[1];
    const float* eps   = (const float*)d_in[2];
    const float* dWg   = (const float*)d_in[3];
    const float* Wih   = (const float*)d_in[4];
    const float* Whh   = (const float*)d_in[5];
    const float* bih   = (const float*)d_in[6];
    const float* bhh   = (const float*)d_in[7];
    const float* encW  = (const float*)d_in[8];
    const float* encb  = (const float*)d_in[9];
    const float* qzW   = (const float*)d_in[10];
    const float* qzb   = (const float*)d_in[11];
    const float* fW1   = (const float*)d_in[12];
    const float* fb1   = (const float*)d_in[13];
    const float* fW2   = (const float*)d_in[14];
    const float* fb2   = (const float*)d_in[15];
    const float* fW3   = (const float*)d_in[16];
    const float* fb3   = (const float*)d_in[17];
    const float* gW1   = (const float*)d_in[18];
    const float* gb1   = (const float*)d_in[19];
    const float* gW2   = (const float*)d_in[20];
    const float* gb2   = (const float*)d_in[21];
    const float* projW = (const float*)d_in[22];
    const float* projb = (const float*)d_in[23];
    const float* pzm   = (const float*)d_in[24];
    const float* pzl   = (const float*)d_in[25];
    float* out = (float*)d_out;

    cudaFuncSetAttribute(gru_kernel, cudaFuncAttributeMaxDynamicSharedMemorySize,
                         GRU_SMEM_FLOATS * 4);
    cudaFuncSetAttribute(enc_kernel, cudaFuncAttributeMaxDynamicSharedMemorySize,
                         (128 * 64 + 64 * 64) * 4);
    cudaFuncSetAttribute(sde_kernel, cudaFuncAttributeMaxDynamicSharedMemorySize,
                         SDE_SMEM_FLOATS * 4);

    gru_kernel<<<128, 384, GRU_SMEM_FLOATS * 4>>>(xs, Wih, Whh, bih, bhh);
    enc_kernel<<<16, 64, (128 * 64 + 64 * 64) * 4>>>(encW, encb, qzW, qzb, eps, pzm, pzl);
    sde_kernel<<<128, 256, SDE_SMEM_FLOATS * 4>>>(extts, dWg, fW1, fb1, fW2, fb2,
                                                  fW3, fb3, gW1, gb1, gW2, gb2);
    dim3 pg(511, 4);
    proj_kernel<<<pg, 256>>>(projW, projb, xs, out);
    final_kernel<<<1, 256>>>(out);
}